// round 3
// baseline (speedup 1.0000x reference)
#include <cuda_runtime.h>

// ============================================================================
// LinearAttentionLayer: B=16, N=8192, F=128, U=128, fp32
// Round 3: packed fma.rn.f32x2 (FFMA2) in all hot GEMM loops -> 2x FMA pipe.
// ============================================================================

namespace {
constexpr int Bb = 16;
constexpr int Nn = 8192;
constexpr int Ff = 128;
constexpr int Uu = 128;
constexpr int ROWS_PER_BLOCK = 128;
constexpr int SUB = 64;
constexpr int CHUNKS = Nn / ROWS_PER_BLOCK;  // 64
}

__device__ float g_kv[Bb * Uu * Uu];

using u64 = unsigned long long;

__device__ __forceinline__ u64 dup2(float v) {
    u64 r;
    asm("mov.b64 %0, {%1, %1};" : "=l"(r) : "f"(v));
    return r;
}
__device__ __forceinline__ void unpack2(u64 p, float& lo, float& hi) {
    asm("mov.b64 {%0, %1}, %2;" : "=f"(lo), "=f"(hi) : "l"(p));
}
__device__ __forceinline__ u64 fma2(u64 a, u64 b, u64 c) {
    u64 d;
    asm("fma.rn.f32x2 %0, %1, %2, %3;" : "=l"(d) : "l"(a), "l"(b), "l"(c));
    return d;
}

// Fast exp: range-reduced 2^e * poly, |y| <= ln2/2. Rel err ~1e-8.
// Avoids MUFU (rt 8/SMSP would dominate at 33.5M calls).
__device__ __forceinline__ float fexp(float x) {
    float t = x * 1.4426950408889634f;
    float r = t + 12582912.0f;
    int   e = __float_as_int(r) - 0x4B400000;
    float f = t - (r - 12582912.0f);
    float y = f * 0.6931471805599453f;
    float p = 1.38888894e-3f;
    p = fmaf(p, y, 8.33333377e-3f);
    p = fmaf(p, y, 4.16666679e-2f);
    p = fmaf(p, y, 1.66666672e-1f);
    p = fmaf(p, y, 0.5f);
    p = fmaf(p, y, 1.0f);
    p = fmaf(p, y, 1.0f);
    return __int_as_float(__float_as_int(p) + (e << 23));
}

__global__ void zero_kv_kernel() {
    int i = blockIdx.x * blockDim.x + threadIdx.x;
    reinterpret_cast<float4*>(g_kv)[i] = make_float4(0.f, 0.f, 0.f, 0.f);
}

// ----------------------------------------------------------------------------
// Packed 64x128 @ 128x128 projection: sOut = maybe_exp(sX @ sW + bias).
// Thread (ty 0..7, tx 0..31) owns rows {ty+8i} x 4 contiguous cols at tx*4.
// W read as ulonglong2 (two f32x2 packs per LDS.128); x as float4 broadcast.
// ----------------------------------------------------------------------------
__device__ __forceinline__ void proj128(
    const float* __restrict__ sX, const float* __restrict__ sW,
    float* __restrict__ sOut, const float* __restrict__ bias_g,
    int ty, int tx, bool do_exp)
{
    const int c0 = tx * 4;
    u64 acc[8][2];
    #pragma unroll
    for (int i = 0; i < 8; ++i) { acc[i][0] = 0ull; acc[i][1] = 0ull; }

    #pragma unroll 2
    for (int f4 = 0; f4 < 128; f4 += 4) {
        float4 xq[8];
        #pragma unroll
        for (int i = 0; i < 8; ++i)
            xq[i] = *reinterpret_cast<const float4*>(&sX[(ty + 8 * i) * 128 + f4]);
        #pragma unroll
        for (int ff = 0; ff < 4; ++ff) {
            ulonglong2 w = *reinterpret_cast<const ulonglong2*>(&sW[(f4 + ff) * 128 + c0]);
            #pragma unroll
            for (int i = 0; i < 8; ++i) {
                float xf = (ff == 0) ? xq[i].x : (ff == 1) ? xq[i].y
                         : (ff == 2) ? xq[i].z : xq[i].w;
                u64 a = dup2(xf);
                acc[i][0] = fma2(a, w.x, acc[i][0]);
                acc[i][1] = fma2(a, w.y, acc[i][1]);
            }
        }
    }

    float4 bb = *reinterpret_cast<const float4*>(&bias_g[c0]);
    #pragma unroll
    for (int i = 0; i < 8; ++i) {
        float v0, v1, v2, v3;
        unpack2(acc[i][0], v0, v1);
        unpack2(acc[i][1], v2, v3);
        v0 += bb.x; v1 += bb.y; v2 += bb.z; v3 += bb.w;
        if (do_exp) { v0 = fexp(v0); v1 = fexp(v1); v2 = fexp(v2); v3 = fexp(v3); }
        *reinterpret_cast<float4*>(&sOut[(ty + 8 * i) * 128 + c0]) =
            make_float4(v0, v1, v2, v3);
    }
}

// ----------------------------------------------------------------------------
// Kernel 1: kv[b] += exp(X @ Wk + bk)^T @ (X @ Wv + bv), chunk of 128 N-rows.
// smem: Wk(64K) + Wv(64K) + X(32K) + K(32K) + V(32K) = 224 KB
// ----------------------------------------------------------------------------
__global__ void __launch_bounds__(256, 1) kv_kernel(
    const float* __restrict__ x,
    const float* __restrict__ Wk, const float* __restrict__ bk,
    const float* __restrict__ Wv, const float* __restrict__ bv)
{
    extern __shared__ float sm[];
    float* sWk = sm;
    float* sWv = sm + 16384;
    float* sX  = sm + 32768;
    float* sK  = sm + 32768 + 8192;
    float* sV  = sm + 32768 + 16384;

    const int tid   = threadIdx.x;
    const int b     = blockIdx.x >> 6;
    const int chunk = blockIdx.x & 63;
    const int n0    = chunk * ROWS_PER_BLOCK;

    {
        const float4* wk4 = reinterpret_cast<const float4*>(Wk);
        const float4* wv4 = reinterpret_cast<const float4*>(Wv);
        float4* sWk4 = reinterpret_cast<float4*>(sWk);
        float4* sWv4 = reinterpret_cast<float4*>(sWv);
        #pragma unroll
        for (int i = 0; i < 16; ++i) {
            sWk4[tid + 256 * i] = wk4[tid + 256 * i];
            sWv4[tid + 256 * i] = wv4[tid + 256 * i];
        }
    }

    const int ty = tid >> 5;
    const int tx = tid & 31;
    const int tu = tid >> 4;     // 0..15: u rows {tu+16i}
    const int tw = tid & 15;     // 0..15: v cols 8 contiguous at tw*8
    const int cv = tw * 8;

    u64 cacc[8][4];
    #pragma unroll
    for (int i = 0; i < 8; ++i)
        #pragma unroll
        for (int j = 0; j < 4; ++j) cacc[i][j] = 0ull;

    const float* xg = x + ((size_t)b * Nn + n0) * Ff;

    for (int s = 0; s < ROWS_PER_BLOCK / SUB; ++s) {
        {
            const float4* xs4 = reinterpret_cast<const float4*>(xg + (size_t)s * SUB * Ff);
            float4* sX4 = reinterpret_cast<float4*>(sX);
            #pragma unroll
            for (int i = 0; i < 8; ++i) sX4[tid + 256 * i] = xs4[tid + 256 * i];
        }
        __syncthreads();   // x visible; prior accumulate done before sK/sV rewrite

        proj128(sX, sWk, sK, bk, ty, tx, true);
        proj128(sX, sWv, sV, bv, ty, tx, false);
        __syncthreads();   // sK/sV ready

        // C[u][v] += sum_r k[r][u] * v[r][v]; v packed along col pairs.
        #pragma unroll 2
        for (int r = 0; r < SUB; ++r) {
            ulonglong2 va = *reinterpret_cast<const ulonglong2*>(&sV[r * 128 + cv]);
            ulonglong2 vb = *reinterpret_cast<const ulonglong2*>(&sV[r * 128 + cv + 4]);
            #pragma unroll
            for (int i = 0; i < 8; ++i) {
                u64 kk = dup2(sK[r * 128 + tu + 16 * i]);
                cacc[i][0] = fma2(kk, va.x, cacc[i][0]);
                cacc[i][1] = fma2(kk, va.y, cacc[i][1]);
                cacc[i][2] = fma2(kk, vb.x, cacc[i][2]);
                cacc[i][3] = fma2(kk, vb.y, cacc[i][3]);
            }
        }
    }

    float* kvb = g_kv + (size_t)b * Uu * Uu;
    #pragma unroll
    for (int i = 0; i < 8; ++i) {
        #pragma unroll
        for (int j = 0; j < 4; ++j) {
            float lo, hi;
            unpack2(cacc[i][j], lo, hi);
            atomicAdd(&kvb[(tu + 16 * i) * Uu + cv + 2 * j],     lo);
            atomicAdd(&kvb[(tu + 16 * i) * Uu + cv + 2 * j + 1], hi);
        }
    }
}

// ----------------------------------------------------------------------------
// Kernel 2: out = exp(X @ Wq + bq) @ kv[b]
// smem: Wq(64K) + kv(64K) + X(32K) + Q(32K) = 192 KB
// ----------------------------------------------------------------------------
__global__ void __launch_bounds__(256, 1) out_kernel(
    const float* __restrict__ x,
    const float* __restrict__ Wq, const float* __restrict__ bq,
    float* __restrict__ out)
{
    extern __shared__ float sm[];
    float* sWq = sm;
    float* sKV = sm + 16384;
    float* sX  = sm + 32768;
    float* sQ  = sm + 40960;

    const int tid   = threadIdx.x;
    const int b     = blockIdx.x >> 6;
    const int chunk = blockIdx.x & 63;
    const int n0    = chunk * ROWS_PER_BLOCK;

    {
        const float4* wq4 = reinterpret_cast<const float4*>(Wq);
        const float4* kv4 = reinterpret_cast<const float4*>(g_kv + (size_t)b * Uu * Uu);
        float4* sWq4 = reinterpret_cast<float4*>(sWq);
        float4* sKV4 = reinterpret_cast<float4*>(sKV);
        #pragma unroll
        for (int i = 0; i < 16; ++i) {
            sWq4[tid + 256 * i] = wq4[tid + 256 * i];
            sKV4[tid + 256 * i] = kv4[tid + 256 * i];
        }
    }

    const int ty = tid >> 5;
    const int tx = tid & 31;
    const int c0 = tx * 4;

    const float* xg = x + ((size_t)b * Nn + n0) * Ff;

    for (int s = 0; s < ROWS_PER_BLOCK / SUB; ++s) {
        {
            const float4* xs4 = reinterpret_cast<const float4*>(xg + (size_t)s * SUB * Ff);
            float4* sX4 = reinterpret_cast<float4*>(sX);
            #pragma unroll
            for (int i = 0; i < 8; ++i) sX4[tid + 256 * i] = xs4[tid + 256 * i];
        }
        __syncthreads();

        proj128(sX, sWq, sQ, bq, ty, tx, true);
        __syncthreads();   // sQ ready

        // out = Q @ kv, packed along col pairs (same shape as proj128,
        // but result goes straight to gmem).
        {
            u64 acc[8][2];
            #pragma unroll
            for (int i = 0; i < 8; ++i) { acc[i][0] = 0ull; acc[i][1] = 0ull; }

            #pragma unroll 2
            for (int u4 = 0; u4 < 128; u4 += 4) {
                float4 qq[8];
                #pragma unroll
                for (int i = 0; i < 8; ++i)
                    qq[i] = *reinterpret_cast<const float4*>(&sQ[(ty + 8 * i) * 128 + u4]);
                #pragma unroll
                for (int ff = 0; ff < 4; ++ff) {
                    ulonglong2 w = *reinterpret_cast<const ulonglong2*>(&sKV[(u4 + ff) * 128 + c0]);
                    #pragma unroll
                    for (int i = 0; i < 8; ++i) {
                        float qf = (ff == 0) ? qq[i].x : (ff == 1) ? qq[i].y
                                 : (ff == 2) ? qq[i].z : qq[i].w;
                        u64 a = dup2(qf);
                        acc[i][0] = fma2(a, w.x, acc[i][0]);
                        acc[i][1] = fma2(a, w.y, acc[i][1]);
                    }
                }
            }

            float* og = out + ((size_t)b * Nn + n0 + (size_t)s * SUB) * Uu;
            #pragma unroll
            for (int i = 0; i < 8; ++i) {
                float v0, v1, v2, v3;
                unpack2(acc[i][0], v0, v1);
                unpack2(acc[i][1], v2, v3);
                *reinterpret_cast<float4*>(&og[(ty + 8 * i) * Uu + c0]) =
                    make_float4(v0, v1, v2, v3);
            }
        }
        // next iteration's sX/sQ rewrites guarded by post-load __syncthreads()
    }
}

// ----------------------------------------------------------------------------
extern "C" void kernel_launch(void* const* d_in, const int* in_sizes, int n_in,
                              void* d_out, int out_size) {
    const float* x  = (const float*)d_in[0];
    const float* Wq = (const float*)d_in[1];
    const float* bq = (const float*)d_in[2];
    const float* Wk = (const float*)d_in[3];
    const float* bk = (const float*)d_in[4];
    const float* Wv = (const float*)d_in[5];
    const float* bv = (const float*)d_in[6];
    float* out = (float*)d_out;

    (void)in_sizes; (void)n_in; (void)out_size;

    constexpr int KV_SMEM  = (16384 * 2 + 8192 * 3) * 4;  // 229376 B
    constexpr int OUT_SMEM = (16384 * 2 + 8192 * 2) * 4;  // 196608 B
    cudaFuncSetAttribute(kv_kernel,  cudaFuncAttributeMaxDynamicSharedMemorySize, KV_SMEM);
    cudaFuncSetAttribute(out_kernel, cudaFuncAttributeMaxDynamicSharedMemorySize, OUT_SMEM);

    zero_kv_kernel<<<256, 256>>>();
    kv_kernel<<<Bb * CHUNKS, 256, KV_SMEM>>>(x, Wk, bk, Wv, bv);
    out_kernel<<<Bb * CHUNKS, 256, OUT_SMEM>>>(x, Wq, bq, out);
}

// round 5
// speedup vs baseline: 2.2719x; 2.2719x over previous
#include <cuda_runtime.h>
#include <cuda_bf16.h>
#include <cstdint>

// ============================================================================
// LinearAttentionLayer B=16,N=8192,F=128,U=128 fp32.
// Baseline-PTX tensor cores: mma.sync.m16n8k16 bf16 + ldmatrix (sm_80 features,
// compile at compute_100 — tcgen05 is unavailable: harness targets sm_100).
// Precision: 2-term bf16 split per operand, 3 accumulating passes (hh+hl+lh)
// into fp32 fragments -> rel err ~1e-5.
//   Stage A: k=exp(x@Wk+bk), v=x@Wv+bv (MMA) -> kv += k^T v (MMA, kv resident
//            in registers per CTA, atomic flush to g_kv)
//   Stage B: q=exp(x@Wq+bq) (MMA) -> out = q@kv (MMA) -> gmem
// ============================================================================

namespace {
constexpr int Bb = 16, Nn = 8192;
constexpr int CHUNK = 1024, SUBT = 64, NSUB = CHUNK / SUBT;   // 16 subtiles
constexpr int NCTA = Bb * (Nn / CHUNK);                       // 128 CTAs

// stage A smem byte offsets (tiles: W* 128x128 bf16 = 32KB; X/K/V 64x128 = 16KB)
constexpr int SA_WKH = 0, SA_WKL = 32768, SA_WVH = 65536, SA_WVL = 98304;
constexpr int SA_XH = 131072, SA_XL = 147456;
constexpr int SA_KH = 163840, SA_KL = 180224, SA_VH = 196608, SA_VL = 212992;
constexpr int SA_BK = 229376, SA_BV = 229888;
constexpr int SA_SMEM = 230400;

// stage B
constexpr int SB_WQH = 0, SB_WQL = 32768, SB_KVH = 65536, SB_KVL = 98304;
constexpr int SB_XH = 131072, SB_XL = 147456, SB_QH = 163840, SB_QL = 180224;
constexpr int SB_BQ = 196608;
constexpr int SB_SMEM = 197120;
}

__device__ float g_kv[Bb * 128 * 128];

// ---------------------------------------------------------------------------
// helpers
// ---------------------------------------------------------------------------
__device__ __forceinline__ uint32_t smem_u32(const void* p) {
    uint32_t a;
    asm("{ .reg .u64 t; cvta.to.shared.u64 t, %1; cvt.u32.u64 %0, t; }" : "=r"(a) : "l"(p));
    return a;
}

// 256B-row tile, XOR-16B swizzle within each 128B half (conflict-free LDSM/STS)
__device__ __forceinline__ uint32_t swz(uint32_t row, uint32_t cb) {
    return row * 256u + (cb & 0x80u) + ((cb & 0x7Fu) ^ ((row & 7u) << 4));
}

__device__ __forceinline__ void ldsm4(uint32_t a, uint32_t* r) {
    asm volatile("ldmatrix.sync.aligned.m8n8.x4.shared.b16 {%0,%1,%2,%3}, [%4];"
        : "=r"(r[0]), "=r"(r[1]), "=r"(r[2]), "=r"(r[3]) : "r"(a));
}
__device__ __forceinline__ void ldsm4t(uint32_t a, uint32_t* r) {
    asm volatile("ldmatrix.sync.aligned.m8n8.x4.trans.shared.b16 {%0,%1,%2,%3}, [%4];"
        : "=r"(r[0]), "=r"(r[1]), "=r"(r[2]), "=r"(r[3]) : "r"(a));
}
__device__ __forceinline__ void mma16816(float* d, const uint32_t* a, const uint32_t* b) {
    asm volatile(
        "mma.sync.aligned.m16n8k16.row.col.f32.bf16.bf16.f32 "
        "{%0,%1,%2,%3}, {%4,%5,%6,%7}, {%8,%9}, {%0,%1,%2,%3};"
        : "+f"(d[0]), "+f"(d[1]), "+f"(d[2]), "+f"(d[3])
        : "r"(a[0]), "r"(a[1]), "r"(a[2]), "r"(a[3]), "r"(b[0]), "r"(b[1]));
}

__device__ __forceinline__ void split2pack(float v0, float v1, uint32_t& hp, uint32_t& lp) {
    __nv_bfloat16 h0 = __float2bfloat16(v0), h1 = __float2bfloat16(v1);
    __nv_bfloat16 l0 = __float2bfloat16(v0 - __bfloat162float(h0));
    __nv_bfloat16 l1 = __float2bfloat16(v1 - __bfloat162float(h1));
    hp = (uint32_t)__bfloat16_as_ushort(h0) | ((uint32_t)__bfloat16_as_ushort(h1) << 16);
    lp = (uint32_t)__bfloat16_as_ushort(l0) | ((uint32_t)__bfloat16_as_ushort(l1) << 16);
}

// fast exp (FMA-only; avoids MUFU). Rel err ~1e-8.
__device__ __forceinline__ float fexp(float x) {
    float t = x * 1.4426950408889634f;
    float r = t + 12582912.0f;
    int   e = __float_as_int(r) - 0x4B400000;
    float y = (t - (r - 12582912.0f)) * 0.6931471805599453f;
    float p = 1.38888894e-3f;
    p = fmaf(p, y, 8.33333377e-3f);
    p = fmaf(p, y, 4.16666679e-2f);
    p = fmaf(p, y, 1.66666672e-1f);
    p = fmaf(p, y, 0.5f);
    p = fmaf(p, y, 1.0f);
    p = fmaf(p, y, 1.0f);
    return __int_as_float(__float_as_int(p) + (e << 23));
}

__global__ void zero_kv_kernel() {
    int i = blockIdx.x * blockDim.x + threadIdx.x;
    reinterpret_cast<float4*>(g_kv)[i] = make_float4(0.f, 0.f, 0.f, 0.f);
}

// ---------------------------------------------------------------------------
// 64x128 = (64x128) @ (128x128) projection tile; warp tile 16x64.
// A = X row-major (ldsm normal), B = W row-major K x N (ldsm trans).
// Result + bias (+exp) split to bf16 hi/lo, stored to swizzled smem [row][col].
// ---------------------------------------------------------------------------
__device__ __forceinline__ void proj_tile(
    char* smem, uint32_t sb,
    int XHo, int XLo, int WHo, int WLo, int OHo, int OLo,
    const float* sbias, bool do_exp, int m0, int c0, int lane)
{
    float acc[8][4];
    #pragma unroll
    for (int i = 0; i < 8; ++i)
        acc[i][0] = acc[i][1] = acc[i][2] = acc[i][3] = 0.f;

    const uint32_t arow = (uint32_t)(m0 + (lane & 15));
    const uint32_t aco  = (uint32_t)((lane >> 4) & 1) * 16;   // bytes
    const uint32_t brow_l = (uint32_t)(lane & 15);
    const uint32_t bco  = (uint32_t)(c0 * 2 + ((lane >> 4) & 1) * 16);

    #pragma unroll
    for (int ks = 0; ks < 8; ++ks) {
        uint32_t ah[4], al[4];
        uint32_t acb = (uint32_t)ks * 32 + aco;
        ldsm4(sb + XHo + swz(arow, acb), ah);
        ldsm4(sb + XLo + swz(arow, acb), al);
        #pragma unroll
        for (int ng = 0; ng < 4; ++ng) {
            uint32_t bh[4], bl[4];
            uint32_t brow = (uint32_t)ks * 16 + brow_l;
            uint32_t bcb  = bco + (uint32_t)ng * 32;
            ldsm4t(sb + WHo + swz(brow, bcb), bh);
            ldsm4t(sb + WLo + swz(brow, bcb), bl);
            mma16816(acc[2 * ng],     ah, bh);
            mma16816(acc[2 * ng + 1], ah, bh + 2);
            mma16816(acc[2 * ng],     al, bh);
            mma16816(acc[2 * ng + 1], al, bh + 2);
            mma16816(acc[2 * ng],     ah, bl);
            mma16816(acc[2 * ng + 1], ah, bl + 2);
        }
    }

    const int r0 = m0 + (lane >> 2);
    const int cb0 = (lane & 3) * 2;
    #pragma unroll
    for (int nf = 0; nf < 8; ++nf) {
        int col = c0 + nf * 8 + cb0;
        float b0 = sbias[col], b1 = sbias[col + 1];
        float v00 = acc[nf][0] + b0, v01 = acc[nf][1] + b1;
        float v10 = acc[nf][2] + b0, v11 = acc[nf][3] + b1;
        if (do_exp) { v00 = fexp(v00); v01 = fexp(v01); v10 = fexp(v10); v11 = fexp(v11); }
        uint32_t hp, lp;
        split2pack(v00, v01, hp, lp);
        *(uint32_t*)(smem + OHo + swz((uint32_t)r0, (uint32_t)col * 2)) = hp;
        *(uint32_t*)(smem + OLo + swz((uint32_t)r0, (uint32_t)col * 2)) = lp;
        split2pack(v10, v11, hp, lp);
        *(uint32_t*)(smem + OHo + swz((uint32_t)(r0 + 8), (uint32_t)col * 2)) = hp;
        *(uint32_t*)(smem + OLo + swz((uint32_t)(r0 + 8), (uint32_t)col * 2)) = lp;
    }
}

// x subtile (64x128 fp32) -> bf16 hi/lo swizzled smem
__device__ __forceinline__ void load_x_tile(
    char* smem, int XHo, int XLo, const float4* xr, int tid)
{
    #pragma unroll
    for (int ii = 0; ii < 8; ++ii) {
        int i = tid + ii * 256;
        uint32_t r  = (uint32_t)(i >> 5);
        uint32_t cb = (uint32_t)(i & 31) * 8;   // 4 bf16 = 8 bytes
        float4 v = xr[i];
        uint32_t hp0, lp0, hp1, lp1;
        split2pack(v.x, v.y, hp0, lp0);
        split2pack(v.z, v.w, hp1, lp1);
        *(uint2*)(smem + XHo + swz(r, cb)) = make_uint2(hp0, hp1);
        *(uint2*)(smem + XLo + swz(r, cb)) = make_uint2(lp0, lp1);
    }
}

// ===========================================================================
// Stage A
// ===========================================================================
__global__ void __launch_bounds__(256, 1) stageA(
    const float* __restrict__ x,
    const float* __restrict__ Wk, const float* __restrict__ bk,
    const float* __restrict__ Wv, const float* __restrict__ bv)
{
    extern __shared__ char smem[];
    const uint32_t sb = smem_u32(smem);
    const int tid = threadIdx.x, warp = tid >> 5, lane = tid & 31;
    const int b = blockIdx.x >> 3, chunk = blockIdx.x & 7;
    const size_t n0 = (size_t)chunk * CHUNK;

    // W split (hi/lo) into swizzled smem, [f][u] row-major
    {
        const float2* wk2 = reinterpret_cast<const float2*>(Wk);
        const float2* wv2 = reinterpret_cast<const float2*>(Wv);
        for (int i = tid; i < 8192; i += 256) {
            uint32_t f  = (uint32_t)(i >> 6);
            uint32_t cb = (uint32_t)(i & 63) * 4;
            float2 a = wk2[i];
            uint32_t hp, lp;
            split2pack(a.x, a.y, hp, lp);
            *(uint32_t*)(smem + SA_WKH + swz(f, cb)) = hp;
            *(uint32_t*)(smem + SA_WKL + swz(f, cb)) = lp;
            a = wv2[i];
            split2pack(a.x, a.y, hp, lp);
            *(uint32_t*)(smem + SA_WVH + swz(f, cb)) = hp;
            *(uint32_t*)(smem + SA_WVL + swz(f, cb)) = lp;
        }
        if (tid < 128) {
            ((float*)(smem + SA_BK))[tid] = bk[tid];
            ((float*)(smem + SA_BV))[tid] = bv[tid];
        }
    }

    // kv accumulator: warp owns u-rows [warp*16, warp*16+16) x 128 cols
    float kvacc[16][4];
    #pragma unroll
    for (int i = 0; i < 16; ++i)
        kvacc[i][0] = kvacc[i][1] = kvacc[i][2] = kvacc[i][3] = 0.f;

    const int m0 = (warp & 3) * 16, c0 = (warp >> 2) * 64;   // proj warp tile
    const int u0 = warp * 16;                                 // kv warp tile

    const float4* xg = reinterpret_cast<const float4*>(x + ((size_t)b * Nn + n0) * 128);

    for (int s = 0; s < NSUB; ++s) {
        load_x_tile(smem, SA_XH, SA_XL, xg + (size_t)s * SUBT * 32, tid);
        __syncthreads();   // x ready; also guarantees prior kv GEMM done before K/V rewrite

        proj_tile(smem, sb, SA_XH, SA_XL, SA_WKH, SA_WKL, SA_KH, SA_KL,
                  (const float*)(smem + SA_BK), true,  m0, c0, lane);
        proj_tile(smem, sb, SA_XH, SA_XL, SA_WVH, SA_WVL, SA_VH, SA_VL,
                  (const float*)(smem + SA_BV), false, m0, c0, lane);
        __syncthreads();   // K/V ready

        // kv += k^T v : A = k^T (trans-load of k[r][u]), B = v[r][w] (trans)
        const uint32_t krow_l = (uint32_t)(((lane >> 4) & 1) * 8 + (lane & 7));
        const uint32_t ucb    = (uint32_t)(u0 + ((lane >> 3) & 1) * 8) * 2;
        #pragma unroll
        for (int ks = 0; ks < 4; ++ks) {
            uint32_t ah[4], al[4];
            uint32_t krow = (uint32_t)ks * 16 + krow_l;
            ldsm4t(sb + SA_KH + swz(krow, ucb), ah);
            ldsm4t(sb + SA_KL + swz(krow, ucb), al);
            #pragma unroll
            for (int ng = 0; ng < 8; ++ng) {
                uint32_t bh[4], bl[4];
                uint32_t brow = (uint32_t)(ks * 16 + (lane & 15));
                uint32_t bcb  = (uint32_t)(ng * 16 + ((lane >> 4) & 1) * 8) * 2;
                ldsm4t(sb + SA_VH + swz(brow, bcb), bh);
                ldsm4t(sb + SA_VL + swz(brow, bcb), bl);
                mma16816(kvacc[2 * ng],     ah, bh);
                mma16816(kvacc[2 * ng + 1], ah, bh + 2);
                mma16816(kvacc[2 * ng],     al, bh);
                mma16816(kvacc[2 * ng + 1], al, bh + 2);
                mma16816(kvacc[2 * ng],     ah, bl);
                mma16816(kvacc[2 * ng + 1], ah, bl + 2);
            }
        }
    }

    // flush kv accumulator (8 chunk-CTAs per batch -> atomic)
    {
        float* kvb = g_kv + (size_t)b * 16384;
        const int ur = u0 + (lane >> 2);
        const int cb0 = (lane & 3) * 2;
        #pragma unroll
        for (int nf = 0; nf < 16; ++nf) {
            int col = nf * 8 + cb0;
            atomicAdd(&kvb[ur * 128 + col],           kvacc[nf][0]);
            atomicAdd(&kvb[ur * 128 + col + 1],       kvacc[nf][1]);
            atomicAdd(&kvb[(ur + 8) * 128 + col],     kvacc[nf][2]);
            atomicAdd(&kvb[(ur + 8) * 128 + col + 1], kvacc[nf][3]);
        }
    }
}

// ===========================================================================
// Stage B
// ===========================================================================
__global__ void __launch_bounds__(256, 1) stageB(
    const float* __restrict__ x,
    const float* __restrict__ Wq, const float* __restrict__ bq,
    float* __restrict__ out)
{
    extern __shared__ char smem[];
    const uint32_t sb = smem_u32(smem);
    const int tid = threadIdx.x, warp = tid >> 5, lane = tid & 31;
    const int b = blockIdx.x >> 3, chunk = blockIdx.x & 7;
    const size_t n0 = (size_t)chunk * CHUNK;

    // Wq and kv split into swizzled smem
    {
        const float2* wq2 = reinterpret_cast<const float2*>(Wq);
        const float2* kv2 = reinterpret_cast<const float2*>(g_kv) + (size_t)b * 8192;
        for (int i = tid; i < 8192; i += 256) {
            uint32_t f  = (uint32_t)(i >> 6);
            uint32_t cb = (uint32_t)(i & 63) * 4;
            float2 a = wq2[i];
            uint32_t hp, lp;
            split2pack(a.x, a.y, hp, lp);
            *(uint32_t*)(smem + SB_WQH + swz(f, cb)) = hp;
            *(uint32_t*)(smem + SB_WQL + swz(f, cb)) = lp;
            a = kv2[i];
            split2pack(a.x, a.y, hp, lp);
            *(uint32_t*)(smem + SB_KVH + swz(f, cb)) = hp;
            *(uint32_t*)(smem + SB_KVL + swz(f, cb)) = lp;
        }
        if (tid < 128)
            ((float*)(smem + SB_BQ))[tid] = bq[tid];
    }

    const int m0 = (warp & 3) * 16, c0 = (warp >> 2) * 64;
    const float4* xg = reinterpret_cast<const float4*>(x + ((size_t)b * Nn + n0) * 128);

    for (int s = 0; s < NSUB; ++s) {
        load_x_tile(smem, SB_XH, SB_XL, xg + (size_t)s * SUBT * 32, tid);
        __syncthreads();   // x ready; prior out-GEMM done before Q rewrite

        proj_tile(smem, sb, SB_XH, SB_XL, SB_WQH, SB_WQL, SB_QH, SB_QL,
                  (const float*)(smem + SB_BQ), true, m0, c0, lane);
        __syncthreads();   // Q ready

        // out = q @ kv : A = q[nn][u] (normal), B = kv[u][w] (trans), K=128
        float oacc[8][4];
        #pragma unroll
        for (int i = 0; i < 8; ++i)
            oacc[i][0] = oacc[i][1] = oacc[i][2] = oacc[i][3] = 0.f;

        const uint32_t arow = (uint32_t)(m0 + (lane & 15));
        const uint32_t aco  = (uint32_t)((lane >> 4) & 1) * 16;
        #pragma unroll
        for (int ks = 0; ks < 8; ++ks) {
            uint32_t ah[4], al[4];
            uint32_t acb = (uint32_t)ks * 32 + aco;
            ldsm4(sb + SB_QH + swz(arow, acb), ah);
            ldsm4(sb + SB_QL + swz(arow, acb), al);
            #pragma unroll
            for (int ng = 0; ng < 4; ++ng) {
                uint32_t bh[4], bl[4];
                uint32_t brow = (uint32_t)(ks * 16 + (lane & 15));
                uint32_t bcb  = (uint32_t)(c0 * 2 + ng * 32 + ((lane >> 4) & 1) * 16);
                ldsm4t(sb + SB_KVH + swz(brow, bcb), bh);
                ldsm4t(sb + SB_KVL + swz(brow, bcb), bl);
                mma16816(oacc[2 * ng],     ah, bh);
                mma16816(oacc[2 * ng + 1], ah, bh + 2);
                mma16816(oacc[2 * ng],     al, bh);
                mma16816(oacc[2 * ng + 1], al, bh + 2);
                mma16816(oacc[2 * ng],     ah, bl);
                mma16816(oacc[2 * ng + 1], ah, bl + 2);
            }
        }

        // store
        float* og = out + ((size_t)b * Nn + n0 + (size_t)s * SUBT) * 128;
        const int r0 = m0 + (lane >> 2);
        const int cb0 = (lane & 3) * 2;
        #pragma unroll
        for (int nf = 0; nf < 8; ++nf) {
            int col = c0 + nf * 8 + cb0;
            *(float2*)(og + (size_t)r0 * 128 + col)       = make_float2(oacc[nf][0], oacc[nf][1]);
            *(float2*)(og + (size_t)(r0 + 8) * 128 + col) = make_float2(oacc[nf][2], oacc[nf][3]);
        }
    }
}

// ---------------------------------------------------------------------------
extern "C" void kernel_launch(void* const* d_in, const int* in_sizes, int n_in,
                              void* d_out, int out_size) {
    const float* x  = (const float*)d_in[0];
    const float* Wq = (const float*)d_in[1];
    const float* bq = (const float*)d_in[2];
    const float* Wk = (const float*)d_in[3];
    const float* bk = (const float*)d_in[4];
    const float* Wv = (const float*)d_in[5];
    const float* bv = (const float*)d_in[6];
    float* out = (float*)d_out;
    (void)in_sizes; (void)n_in; (void)out_size;

    cudaFuncSetAttribute(stageA, cudaFuncAttributeMaxDynamicSharedMemorySize, SA_SMEM);
    cudaFuncSetAttribute(stageB, cudaFuncAttributeMaxDynamicSharedMemorySize, SB_SMEM);

    zero_kv_kernel<<<256, 256>>>();
    stageA<<<NCTA, 256, SA_SMEM>>>(x, Wk, bk, Wv, bv);
    stageB<<<NCTA, 256, SB_SMEM>>>(x, Wq, bq, out);
}

// round 6
// speedup vs baseline: 2.8544x; 1.2564x over previous
#include <cuda_runtime.h>
#include <cuda_bf16.h>
#include <cstdint>

// ============================================================================
// LinearAttentionLayer B=16,N=8192,F=128,U=128 fp32.
// mma.sync.m16n8k16 bf16 + ldmatrix, 2-term bf16 split (hh+hl+lh) -> ~6e-6.
// Round 6: +register prefetch of x tiles, +cvt.bf16x2 packing epilogue,
//          +148-CTA contiguous task rebalance (2048 subtile tasks).
// ============================================================================

namespace {
constexpr int Bb = 16, Nn = 8192;
constexpr int SUBT = 64;
constexpr int TASKS = Bb * (Nn / SUBT);   // 2048
constexpr int GRID  = 148;
constexpr int SPB   = Nn / SUBT;          // 128 subtiles per batch

// stage A smem byte offsets
constexpr int SA_WKH = 0, SA_WKL = 32768, SA_WVH = 65536, SA_WVL = 98304;
constexpr int SA_XH = 131072, SA_XL = 147456;
constexpr int SA_KH = 163840, SA_KL = 180224, SA_VH = 196608, SA_VL = 212992;
constexpr int SA_BK = 229376, SA_BV = 229888;
constexpr int SA_SMEM = 230400;

// stage B
constexpr int SB_WQH = 0, SB_WQL = 32768, SB_KVH = 65536, SB_KVL = 98304;
constexpr int SB_XH = 131072, SB_XL = 147456, SB_QH = 163840, SB_QL = 180224;
constexpr int SB_BQ = 196608;
constexpr int SB_SMEM = 197120;
}

__device__ float g_kv[Bb * 128 * 128];

// ---------------------------------------------------------------------------
__device__ __forceinline__ uint32_t smem_u32(const void* p) {
    uint32_t a;
    asm("{ .reg .u64 t; cvta.to.shared.u64 t, %1; cvt.u32.u64 %0, t; }" : "=r"(a) : "l"(p));
    return a;
}
// 256B-row tile, XOR-16B swizzle within each 128B half
__device__ __forceinline__ uint32_t swz(uint32_t row, uint32_t cb) {
    return row * 256u + (cb & 0x80u) + ((cb & 0x7Fu) ^ ((row & 7u) << 4));
}
__device__ __forceinline__ void ldsm4(uint32_t a, uint32_t* r) {
    asm volatile("ldmatrix.sync.aligned.m8n8.x4.shared.b16 {%0,%1,%2,%3}, [%4];"
        : "=r"(r[0]), "=r"(r[1]), "=r"(r[2]), "=r"(r[3]) : "r"(a));
}
__device__ __forceinline__ void ldsm4t(uint32_t a, uint32_t* r) {
    asm volatile("ldmatrix.sync.aligned.m8n8.x4.trans.shared.b16 {%0,%1,%2,%3}, [%4];"
        : "=r"(r[0]), "=r"(r[1]), "=r"(r[2]), "=r"(r[3]) : "r"(a));
}
__device__ __forceinline__ void mma16816(float* d, const uint32_t* a, const uint32_t* b) {
    asm volatile(
        "mma.sync.aligned.m16n8k16.row.col.f32.bf16.bf16.f32 "
        "{%0,%1,%2,%3}, {%4,%5,%6,%7}, {%8,%9}, {%0,%1,%2,%3};"
        : "+f"(d[0]), "+f"(d[1]), "+f"(d[2]), "+f"(d[3])
        : "r"(a[0]), "r"(a[1]), "r"(a[2]), "r"(a[3]), "r"(b[0]), "r"(b[1]));
}

// hi/lo bf16 split of a pair, packed; hi recovery via ALU-pipe bit ops.
__device__ __forceinline__ void split2pack(float v0, float v1, uint32_t& hp, uint32_t& lp) {
    asm("cvt.rn.bf16x2.f32 %0, %1, %2;" : "=r"(hp) : "f"(v1), "f"(v0));
    float h0 = __int_as_float(hp << 16);
    float h1 = __int_as_float(hp & 0xFFFF0000u);
    float l0 = v0 - h0, l1 = v1 - h1;
    asm("cvt.rn.bf16x2.f32 %0, %1, %2;" : "=r"(lp) : "f"(l1), "f"(l0));
}

// fast exp (FMA-only). Rel err ~1e-8.
__device__ __forceinline__ float fexp(float x) {
    float t = x * 1.4426950408889634f;
    float r = t + 12582912.0f;
    int   e = __float_as_int(r) - 0x4B400000;
    float y = (t - (r - 12582912.0f)) * 0.6931471805599453f;
    float p = 1.38888894e-3f;
    p = fmaf(p, y, 8.33333377e-3f);
    p = fmaf(p, y, 4.16666679e-2f);
    p = fmaf(p, y, 1.66666672e-1f);
    p = fmaf(p, y, 0.5f);
    p = fmaf(p, y, 1.0f);
    p = fmaf(p, y, 1.0f);
    return __int_as_float(__float_as_int(p) + (e << 23));
}

__global__ void zero_kv_kernel() {
    int i = blockIdx.x * blockDim.x + threadIdx.x;
    reinterpret_cast<float4*>(g_kv)[i] = make_float4(0.f, 0.f, 0.f, 0.f);
}

// ---------------------------------------------------------------------------
// 64x128 = (64x128) @ (128x128) proj; warp tile 16x64. 3-pass split MMA.
// ---------------------------------------------------------------------------
__device__ __forceinline__ void proj_tile(
    char* smem, uint32_t sb,
    int XHo, int XLo, int WHo, int WLo, int OHo, int OLo,
    const float* sbias, bool do_exp, int m0, int c0, int lane)
{
    float acc[8][4];
    #pragma unroll
    for (int i = 0; i < 8; ++i)
        acc[i][0] = acc[i][1] = acc[i][2] = acc[i][3] = 0.f;

    const uint32_t arow = (uint32_t)(m0 + (lane & 15));
    const uint32_t aco  = (uint32_t)((lane >> 4) & 1) * 16;
    const uint32_t brow_l = (uint32_t)(lane & 15);
    const uint32_t bco  = (uint32_t)(c0 * 2 + ((lane >> 4) & 1) * 16);

    #pragma unroll
    for (int ks = 0; ks < 8; ++ks) {
        uint32_t ah[4], al[4];
        uint32_t acb = (uint32_t)ks * 32 + aco;
        ldsm4(sb + XHo + swz(arow, acb), ah);
        ldsm4(sb + XLo + swz(arow, acb), al);
        #pragma unroll
        for (int ng = 0; ng < 4; ++ng) {
            uint32_t bh[4], bl[4];
            uint32_t brow = (uint32_t)ks * 16 + brow_l;
            uint32_t bcb  = bco + (uint32_t)ng * 32;
            ldsm4t(sb + WHo + swz(brow, bcb), bh);
            ldsm4t(sb + WLo + swz(brow, bcb), bl);
            mma16816(acc[2 * ng],     ah, bh);
            mma16816(acc[2 * ng + 1], ah, bh + 2);
            mma16816(acc[2 * ng],     al, bh);
            mma16816(acc[2 * ng + 1], al, bh + 2);
            mma16816(acc[2 * ng],     ah, bl);
            mma16816(acc[2 * ng + 1], ah, bl + 2);
        }
    }

    const int r0 = m0 + (lane >> 2);
    const int cb0 = (lane & 3) * 2;
    #pragma unroll
    for (int nf = 0; nf < 8; ++nf) {
        int col = c0 + nf * 8 + cb0;
        float b0 = sbias[col], b1 = sbias[col + 1];
        float v00 = acc[nf][0] + b0, v01 = acc[nf][1] + b1;
        float v10 = acc[nf][2] + b0, v11 = acc[nf][3] + b1;
        if (do_exp) { v00 = fexp(v00); v01 = fexp(v01); v10 = fexp(v10); v11 = fexp(v11); }
        uint32_t hp, lp;
        split2pack(v00, v01, hp, lp);
        *(uint32_t*)(smem + OHo + swz((uint32_t)r0, (uint32_t)col * 2)) = hp;
        *(uint32_t*)(smem + OLo + swz((uint32_t)r0, (uint32_t)col * 2)) = lp;
        split2pack(v10, v11, hp, lp);
        *(uint32_t*)(smem + OHo + swz((uint32_t)(r0 + 8), (uint32_t)col * 2)) = hp;
        *(uint32_t*)(smem + OLo + swz((uint32_t)(r0 + 8), (uint32_t)col * 2)) = lp;
    }
}

// convert prefetched x regs (64x128 fp32 tile) -> bf16 hi/lo swizzled smem
__device__ __forceinline__ void store_x_regs(
    char* smem, int XHo, int XLo, const float4* xr, int tid)
{
    #pragma unroll
    for (int ii = 0; ii < 8; ++ii) {
        int i = tid + ii * 256;
        uint32_t r  = (uint32_t)(i >> 5);
        uint32_t cb = (uint32_t)(i & 31) * 8;
        float4 v = xr[ii];
        uint32_t hp0, lp0, hp1, lp1;
        split2pack(v.x, v.y, hp0, lp0);
        split2pack(v.z, v.w, hp1, lp1);
        *(uint2*)(smem + XHo + swz(r, cb)) = make_uint2(hp0, hp1);
        *(uint2*)(smem + XLo + swz(r, cb)) = make_uint2(lp0, lp1);
    }
}

// ===========================================================================
// Stage A: tasks t in [task0,task1), b = t/128. kv register accumulator,
// flushed atomically per batch switch.
// ===========================================================================
__global__ void __launch_bounds__(256, 1) stageA(
    const float* __restrict__ x,
    const float* __restrict__ Wk, const float* __restrict__ bk,
    const float* __restrict__ Wv, const float* __restrict__ bv)
{
    extern __shared__ char smem[];
    const uint32_t sb = smem_u32(smem);
    const int tid = threadIdx.x, warp = tid >> 5, lane = tid & 31;

    const int task0 = (int)((long)blockIdx.x * TASKS / GRID);
    const int task1 = (int)((long)(blockIdx.x + 1) * TASKS / GRID);

    // W split into swizzled smem
    {
        const float2* wk2 = reinterpret_cast<const float2*>(Wk);
        const float2* wv2 = reinterpret_cast<const float2*>(Wv);
        for (int i = tid; i < 8192; i += 256) {
            uint32_t f  = (uint32_t)(i >> 6);
            uint32_t cb = (uint32_t)(i & 63) * 4;
            float2 a = wk2[i];
            uint32_t hp, lp;
            split2pack(a.x, a.y, hp, lp);
            *(uint32_t*)(smem + SA_WKH + swz(f, cb)) = hp;
            *(uint32_t*)(smem + SA_WKL + swz(f, cb)) = lp;
            a = wv2[i];
            split2pack(a.x, a.y, hp, lp);
            *(uint32_t*)(smem + SA_WVH + swz(f, cb)) = hp;
            *(uint32_t*)(smem + SA_WVL + swz(f, cb)) = lp;
        }
        if (tid < 128) {
            ((float*)(smem + SA_BK))[tid] = bk[tid];
            ((float*)(smem + SA_BV))[tid] = bv[tid];
        }
    }

    float kvacc[16][4];
    #pragma unroll
    for (int i = 0; i < 16; ++i)
        kvacc[i][0] = kvacc[i][1] = kvacc[i][2] = kvacc[i][3] = 0.f;

    const int m0 = (warp & 3) * 16, c0 = (warp >> 2) * 64;
    const int u0 = warp * 16;
    const int ur = u0 + (lane >> 2);
    const int cb0 = (lane & 3) * 2;

    const float4* xall = reinterpret_cast<const float4*>(x);

    // preload first tile
    float4 xr[8];
    if (task0 < task1) {
        #pragma unroll
        for (int ii = 0; ii < 8; ++ii)
            xr[ii] = xall[(size_t)task0 * 2048 + ii * 256 + tid];
    }

    int bcur = task0 >> 7;
    for (int t = task0; t < task1; ++t) {
        const int b = t >> 7;
        if (b != bcur) {
            // flush + reset register kv (per-warp, atomic)
            float* kvb = g_kv + (size_t)bcur * 16384;
            #pragma unroll
            for (int nf = 0; nf < 16; ++nf) {
                int col = nf * 8 + cb0;
                atomicAdd(&kvb[ur * 128 + col],           kvacc[nf][0]);
                atomicAdd(&kvb[ur * 128 + col + 1],       kvacc[nf][1]);
                atomicAdd(&kvb[(ur + 8) * 128 + col],     kvacc[nf][2]);
                atomicAdd(&kvb[(ur + 8) * 128 + col + 1], kvacc[nf][3]);
                kvacc[nf][0] = kvacc[nf][1] = kvacc[nf][2] = kvacc[nf][3] = 0.f;
            }
            bcur = b;
        }

        store_x_regs(smem, SA_XH, SA_XL, xr, tid);
        if (t + 1 < task1) {       // prefetch next tile; drains behind MMA phases
            #pragma unroll
            for (int ii = 0; ii < 8; ++ii)
                xr[ii] = xall[(size_t)(t + 1) * 2048 + ii * 256 + tid];
        }
        __syncthreads();   // X ready; all warps past prior proj's X reads

        proj_tile(smem, sb, SA_XH, SA_XL, SA_WKH, SA_WKL, SA_KH, SA_KL,
                  (const float*)(smem + SA_BK), true,  m0, c0, lane);
        proj_tile(smem, sb, SA_XH, SA_XL, SA_WVH, SA_WVL, SA_VH, SA_VL,
                  (const float*)(smem + SA_BV), false, m0, c0, lane);
        __syncthreads();   // K/V ready

        // kv += k^T v
        const uint32_t krow_l = (uint32_t)(((lane >> 4) & 1) * 8 + (lane & 7));
        const uint32_t ucb    = (uint32_t)(u0 + ((lane >> 3) & 1) * 8) * 2;
        #pragma unroll
        for (int ks = 0; ks < 4; ++ks) {
            uint32_t ah[4], al[4];
            uint32_t krow = (uint32_t)ks * 16 + krow_l;
            ldsm4t(sb + SA_KH + swz(krow, ucb), ah);
            ldsm4t(sb + SA_KL + swz(krow, ucb), al);
            #pragma unroll
            for (int ng = 0; ng < 8; ++ng) {
                uint32_t bh[4], bl[4];
                uint32_t brow = (uint32_t)(ks * 16 + (lane & 15));
                uint32_t bcb  = (uint32_t)(ng * 16 + ((lane >> 4) & 1) * 8) * 2;
                ldsm4t(sb + SA_VH + swz(brow, bcb), bh);
                ldsm4t(sb + SA_VL + swz(brow, bcb), bl);
                mma16816(kvacc[2 * ng],     ah, bh);
                mma16816(kvacc[2 * ng + 1], ah, bh + 2);
                mma16816(kvacc[2 * ng],     al, bh);
                mma16816(kvacc[2 * ng + 1], al, bh + 2);
                mma16816(kvacc[2 * ng],     ah, bl);
                mma16816(kvacc[2 * ng + 1], ah, bl + 2);
            }
        }
    }

    // final flush
    {
        float* kvb = g_kv + (size_t)bcur * 16384;
        #pragma unroll
        for (int nf = 0; nf < 16; ++nf) {
            int col = nf * 8 + cb0;
            atomicAdd(&kvb[ur * 128 + col],           kvacc[nf][0]);
            atomicAdd(&kvb[ur * 128 + col + 1],       kvacc[nf][1]);
            atomicAdd(&kvb[(ur + 8) * 128 + col],     kvacc[nf][2]);
            atomicAdd(&kvb[(ur + 8) * 128 + col + 1], kvacc[nf][3]);
        }
    }
}

// ===========================================================================
// Stage B: out tile per task; kv smem tile reloaded on batch switch.
// ===========================================================================
__global__ void __launch_bounds__(256, 1) stageB(
    const float* __restrict__ x,
    const float* __restrict__ Wq, const float* __restrict__ bq,
    float* __restrict__ out)
{
    extern __shared__ char smem[];
    const uint32_t sb = smem_u32(smem);
    const int tid = threadIdx.x, warp = tid >> 5, lane = tid & 31;

    const int task0 = (int)((long)blockIdx.x * TASKS / GRID);
    const int task1 = (int)((long)(blockIdx.x + 1) * TASKS / GRID);

    // Wq split
    {
        const float2* wq2 = reinterpret_cast<const float2*>(Wq);
        for (int i = tid; i < 8192; i += 256) {
            uint32_t f  = (uint32_t)(i >> 6);
            uint32_t cb = (uint32_t)(i & 63) * 4;
            float2 a = wq2[i];
            uint32_t hp, lp;
            split2pack(a.x, a.y, hp, lp);
            *(uint32_t*)(smem + SB_WQH + swz(f, cb)) = hp;
            *(uint32_t*)(smem + SB_WQL + swz(f, cb)) = lp;
        }
        if (tid < 128)
            ((float*)(smem + SB_BQ))[tid] = bq[tid];
    }

    const int m0 = (warp & 3) * 16, c0 = (warp >> 2) * 64;
    const float4* xall = reinterpret_cast<const float4*>(x);

    float4 xr[8];
    if (task0 < task1) {
        #pragma unroll
        for (int ii = 0; ii < 8; ++ii)
            xr[ii] = xall[(size_t)task0 * 2048 + ii * 256 + tid];
    }

    int bcur = -1;
    for (int t = task0; t < task1; ++t) {
        const int b = t >> 7;

        store_x_regs(smem, SB_XH, SB_XL, xr, tid);
        if (t + 1 < task1) {
            #pragma unroll
            for (int ii = 0; ii < 8; ++ii)
                xr[ii] = xall[(size_t)(t + 1) * 2048 + ii * 256 + tid];
        }
        __syncthreads();   // X ready; all warps past prior out-GEMM (KV reads)

        if (b != bcur) {   // (re)load kv tile; visibility via the next sync
            const float2* kv2 = reinterpret_cast<const float2*>(g_kv) + (size_t)b * 8192;
            for (int i = tid; i < 8192; i += 256) {
                uint32_t f  = (uint32_t)(i >> 6);
                uint32_t cb = (uint32_t)(i & 63) * 4;
                float2 a = kv2[i];
                uint32_t hp, lp;
                split2pack(a.x, a.y, hp, lp);
                *(uint32_t*)(smem + SB_KVH + swz(f, cb)) = hp;
                *(uint32_t*)(smem + SB_KVL + swz(f, cb)) = lp;
            }
            bcur = b;
        }

        proj_tile(smem, sb, SB_XH, SB_XL, SB_WQH, SB_WQL, SB_QH, SB_QL,
                  (const float*)(smem + SB_BQ), true, m0, c0, lane);
        __syncthreads();   // Q (and any reloaded KV) ready

        // out = q @ kv
        float oacc[8][4];
        #pragma unroll
        for (int i = 0; i < 8; ++i)
            oacc[i][0] = oacc[i][1] = oacc[i][2] = oacc[i][3] = 0.f;

        const uint32_t arow = (uint32_t)(m0 + (lane & 15));
        const uint32_t aco  = (uint32_t)((lane >> 4) & 1) * 16;
        #pragma unroll
        for (int ks = 0; ks < 8; ++ks) {
            uint32_t ah[4], al[4];
            uint32_t acb = (uint32_t)ks * 32 + aco;
            ldsm4(sb + SB_QH + swz(arow, acb), ah);
            ldsm4(sb + SB_QL + swz(arow, acb), al);
            #pragma unroll
            for (int ng = 0; ng < 4; ++ng) {
                uint32_t bh[4], bl[4];
                uint32_t brow = (uint32_t)(ks * 16 + (lane & 15));
                uint32_t bcb  = (uint32_t)(c0 * 2 + ng * 32 + ((lane >> 4) & 1) * 16);
                ldsm4t(sb + SB_KVH + swz(brow, bcb), bh);
                ldsm4t(sb + SB_KVL + swz(brow, bcb), bl);
                mma16816(oacc[2 * ng],     ah, bh);
                mma16816(oacc[2 * ng + 1], ah, bh + 2);
                mma16816(oacc[2 * ng],     al, bh);
                mma16816(oacc[2 * ng + 1], al, bh + 2);
                mma16816(oacc[2 * ng],     ah, bl);
                mma16816(oacc[2 * ng + 1], ah, bl + 2);
            }
        }

        float* og = out + (size_t)t * 8192;
        const int r0 = m0 + (lane >> 2);
        const int cb0 = (lane & 3) * 2;
        #pragma unroll
        for (int nf = 0; nf < 8; ++nf) {
            int col = c0 + nf * 8 + cb0;
            *(float2*)(og + (size_t)r0 * 128 + col)       = make_float2(oacc[nf][0], oacc[nf][1]);
            *(float2*)(og + (size_t)(r0 + 8) * 128 + col) = make_float2(oacc[nf][2], oacc[nf][3]);
        }
    }
}

// ---------------------------------------------------------------------------
extern "C" void kernel_launch(void* const* d_in, const int* in_sizes, int n_in,
                              void* d_out, int out_size) {
    const float* x  = (const float*)d_in[0];
    const float* Wq = (const float*)d_in[1];
    const float* bq = (const float*)d_in[2];
    const float* Wk = (const float*)d_in[3];
    const float* bk = (const float*)d_in[4];
    const float* Wv = (const float*)d_in[5];
    const float* bv = (const float*)d_in[6];
    float* out = (float*)d_out;
    (void)in_sizes; (void)n_in; (void)out_size;

    cudaFuncSetAttribute(stageA, cudaFuncAttributeMaxDynamicSharedMemorySize, SA_SMEM);
    cudaFuncSetAttribute(stageB, cudaFuncAttributeMaxDynamicSharedMemorySize, SB_SMEM);

    zero_kv_kernel<<<256, 256>>>();
    stageA<<<GRID, 256, SA_SMEM>>>(x, Wk, bk, Wv, bv);
    stageB<<<GRID, 256, SB_SMEM>>>(x, Wq, bq, out);
}

// round 7
// speedup vs baseline: 3.0645x; 1.0736x over previous
#include <cuda_runtime.h>
#include <cuda_bf16.h>
#include <cstdint>

// ============================================================================
// LinearAttentionLayer B=16,N=8192,F=128,U=128 fp32.
// mma.sync.m16n8k16 bf16 + ldmatrix, 2-term bf16 split (hh+hl+lh) ~6e-6.
// Round 7: smem-port rebalance — 32x32 proj warp tiles (fused K/V proj in
// stage A, shared X fragments), 32x64 kv tiles, 32x32 out tiles. Cuts LDSM
// traffic ~35% (the measured bottleneck); MMA count unchanged.
// ============================================================================

namespace {
constexpr int Bb = 16, Nn = 8192;
constexpr int SUBT = 64;
constexpr int TASKS = Bb * (Nn / SUBT);   // 2048
constexpr int GRID  = 148;

constexpr int SA_WKH = 0, SA_WKL = 32768, SA_WVH = 65536, SA_WVL = 98304;
constexpr int SA_XH = 131072, SA_XL = 147456;
constexpr int SA_KH = 163840, SA_KL = 180224, SA_VH = 196608, SA_VL = 212992;
constexpr int SA_BK = 229376, SA_BV = 229888;
constexpr int SA_SMEM = 230400;

constexpr int SB_WQH = 0, SB_WQL = 32768, SB_KVH = 65536, SB_KVL = 98304;
constexpr int SB_XH = 131072, SB_XL = 147456, SB_QH = 163840, SB_QL = 180224;
constexpr int SB_BQ = 196608;
constexpr int SB_SMEM = 197120;
}

__device__ float g_kv[Bb * 128 * 128];

// ---------------------------------------------------------------------------
__device__ __forceinline__ uint32_t smem_u32(const void* p) {
    uint32_t a;
    asm("{ .reg .u64 t; cvta.to.shared.u64 t, %1; cvt.u32.u64 %0, t; }" : "=r"(a) : "l"(p));
    return a;
}
__device__ __forceinline__ uint32_t swz(uint32_t row, uint32_t cb) {
    return row * 256u + (cb & 0x80u) + ((cb & 0x7Fu) ^ ((row & 7u) << 4));
}
__device__ __forceinline__ void ldsm4(uint32_t a, uint32_t* r) {
    asm volatile("ldmatrix.sync.aligned.m8n8.x4.shared.b16 {%0,%1,%2,%3}, [%4];"
        : "=r"(r[0]), "=r"(r[1]), "=r"(r[2]), "=r"(r[3]) : "r"(a));
}
__device__ __forceinline__ void ldsm4t(uint32_t a, uint32_t* r) {
    asm volatile("ldmatrix.sync.aligned.m8n8.x4.trans.shared.b16 {%0,%1,%2,%3}, [%4];"
        : "=r"(r[0]), "=r"(r[1]), "=r"(r[2]), "=r"(r[3]) : "r"(a));
}
__device__ __forceinline__ void mma16816(float* d, const uint32_t* a, const uint32_t* b) {
    asm volatile(
        "mma.sync.aligned.m16n8k16.row.col.f32.bf16.bf16.f32 "
        "{%0,%1,%2,%3}, {%4,%5,%6,%7}, {%8,%9}, {%0,%1,%2,%3};"
        : "+f"(d[0]), "+f"(d[1]), "+f"(d[2]), "+f"(d[3])
        : "r"(a[0]), "r"(a[1]), "r"(a[2]), "r"(a[3]), "r"(b[0]), "r"(b[1]));
}
// 3-pass split MMA into a 16x16 output (two n8 accs d0,d1)
__device__ __forceinline__ void mma3(float* d0, float* d1,
    const uint32_t* ah, const uint32_t* al, const uint32_t* bh, const uint32_t* bl) {
    mma16816(d0, ah, bh); mma16816(d1, ah, bh + 2);
    mma16816(d0, al, bh); mma16816(d1, al, bh + 2);
    mma16816(d0, ah, bl); mma16816(d1, ah, bl + 2);
}

__device__ __forceinline__ void split2pack(float v0, float v1, uint32_t& hp, uint32_t& lp) {
    asm("cvt.rn.bf16x2.f32 %0, %1, %2;" : "=r"(hp) : "f"(v1), "f"(v0));
    float h0 = __int_as_float(hp << 16);
    float h1 = __int_as_float(hp & 0xFFFF0000u);
    float l0 = v0 - h0, l1 = v1 - h1;
    asm("cvt.rn.bf16x2.f32 %0, %1, %2;" : "=r"(lp) : "f"(l1), "f"(l0));
}

__device__ __forceinline__ float fexp(float x) {
    float t = x * 1.4426950408889634f;
    float r = t + 12582912.0f;
    int   e = __float_as_int(r) - 0x4B400000;
    float y = (t - (r - 12582912.0f)) * 0.6931471805599453f;
    float p = 1.38888894e-3f;
    p = fmaf(p, y, 8.33333377e-3f);
    p = fmaf(p, y, 4.16666679e-2f);
    p = fmaf(p, y, 1.66666672e-1f);
    p = fmaf(p, y, 0.5f);
    p = fmaf(p, y, 1.0f);
    p = fmaf(p, y, 1.0f);
    return __int_as_float(__float_as_int(p) + (e << 23));
}

__global__ void zero_kv_kernel() {
    int i = blockIdx.x * blockDim.x + threadIdx.x;
    reinterpret_cast<float4*>(g_kv)[i] = make_float4(0.f, 0.f, 0.f, 0.f);
}

// prefetched x regs (64x128 fp32 tile) -> bf16 hi/lo swizzled smem
__device__ __forceinline__ void store_x_regs(
    char* smem, int XHo, int XLo, const float4* xr, int tid)
{
    #pragma unroll
    for (int ii = 0; ii < 8; ++ii) {
        int i = tid + ii * 256;
        uint32_t r  = (uint32_t)(i >> 5);
        uint32_t cb = (uint32_t)(i & 31) * 8;
        float4 v = xr[ii];
        uint32_t hp0, lp0, hp1, lp1;
        split2pack(v.x, v.y, hp0, lp0);
        split2pack(v.z, v.w, hp1, lp1);
        *(uint2*)(smem + XHo + swz(r, cb)) = make_uint2(hp0, hp1);
        *(uint2*)(smem + XLo + swz(r, cb)) = make_uint2(lp0, lp1);
    }
}

// ===========================================================================
// Stage A
// ===========================================================================
__global__ void __launch_bounds__(256, 1) stageA(
    const float* __restrict__ x,
    const float* __restrict__ Wk, const float* __restrict__ bk,
    const float* __restrict__ Wv, const float* __restrict__ bv)
{
    extern __shared__ char smem[];
    const uint32_t sb = smem_u32(smem);
    const int tid = threadIdx.x, warp = tid >> 5, lane = tid & 31;

    const int task0 = (int)((long)blockIdx.x * TASKS / GRID);
    const int task1 = (int)((long)(blockIdx.x + 1) * TASKS / GRID);

    // W split into swizzled smem
    {
        const float2* wk2 = reinterpret_cast<const float2*>(Wk);
        const float2* wv2 = reinterpret_cast<const float2*>(Wv);
        for (int i = tid; i < 8192; i += 256) {
            uint32_t f  = (uint32_t)(i >> 6);
            uint32_t cb = (uint32_t)(i & 63) * 4;
            float2 a = wk2[i];
            uint32_t hp, lp;
            split2pack(a.x, a.y, hp, lp);
            *(uint32_t*)(smem + SA_WKH + swz(f, cb)) = hp;
            *(uint32_t*)(smem + SA_WKL + swz(f, cb)) = lp;
            a = wv2[i];
            split2pack(a.x, a.y, hp, lp);
            *(uint32_t*)(smem + SA_WVH + swz(f, cb)) = hp;
            *(uint32_t*)(smem + SA_WVL + swz(f, cb)) = lp;
        }
        if (tid < 128) {
            ((float*)(smem + SA_BK))[tid] = bk[tid];
            ((float*)(smem + SA_BV))[tid] = bv[tid];
        }
    }

    // warp coords: proj tile 32x32; kv tile 32u x 64w
    const int pm0 = (warp >> 2) * 32, pc0 = (warp & 3) * 32;
    const int u0  = (warp & 3) * 32,  w0  = (warp >> 2) * 64;
    const int er = lane >> 2, ec = 2 * (lane & 3);

    float kvacc[2][8][4];
    #pragma unroll
    for (int mb = 0; mb < 2; ++mb)
        #pragma unroll
        for (int nb = 0; nb < 8; ++nb)
            kvacc[mb][nb][0] = kvacc[mb][nb][1] = kvacc[mb][nb][2] = kvacc[mb][nb][3] = 0.f;

    const float* sbk = (const float*)(smem + SA_BK);
    const float* sbv = (const float*)(smem + SA_BV);
    const float4* xall = reinterpret_cast<const float4*>(x);

    float4 xr[8];
    #pragma unroll
    for (int ii = 0; ii < 8; ++ii)
        xr[ii] = xall[(size_t)task0 * 2048 + ii * 256 + tid];

    int bcur = task0 >> 7;
    for (int t = task0; t < task1; ++t) {
        const int b = t >> 7;
        if (b != bcur) {
            float* kvb = g_kv + (size_t)bcur * 16384;
            #pragma unroll
            for (int mb = 0; mb < 2; ++mb) {
                int ur = u0 + mb * 16 + er;
                #pragma unroll
                for (int nb = 0; nb < 8; ++nb) {
                    int col = w0 + nb * 8 + ec;
                    atomicAdd(&kvb[ur * 128 + col],           kvacc[mb][nb][0]);
                    atomicAdd(&kvb[ur * 128 + col + 1],       kvacc[mb][nb][1]);
                    atomicAdd(&kvb[(ur + 8) * 128 + col],     kvacc[mb][nb][2]);
                    atomicAdd(&kvb[(ur + 8) * 128 + col + 1], kvacc[mb][nb][3]);
                    kvacc[mb][nb][0] = kvacc[mb][nb][1] = kvacc[mb][nb][2] = kvacc[mb][nb][3] = 0.f;
                }
            }
            bcur = b;
        }

        store_x_regs(smem, SA_XH, SA_XL, xr, tid);
        if (t + 1 < task1) {
            #pragma unroll
            for (int ii = 0; ii < 8; ++ii)
                xr[ii] = xall[(size_t)(t + 1) * 2048 + ii * 256 + tid];
        }
        __syncthreads();   // X ready; all warps done with prior kv phase

        // ---- fused K/V projection, warp tile 32x32 ----
        float ka[2][4][4], va[2][4][4];
        #pragma unroll
        for (int mb = 0; mb < 2; ++mb)
            #pragma unroll
            for (int nb = 0; nb < 4; ++nb) {
                ka[mb][nb][0] = ka[mb][nb][1] = ka[mb][nb][2] = ka[mb][nb][3] = 0.f;
                va[mb][nb][0] = va[mb][nb][1] = va[mb][nb][2] = va[mb][nb][3] = 0.f;
            }
        {
            const uint32_t arow0 = (uint32_t)(pm0 + (lane & 15));
            const uint32_t aco   = (uint32_t)((lane >> 4) & 1) * 16;
            const uint32_t brl   = (uint32_t)(lane & 15);
            #pragma unroll
            for (int ks = 0; ks < 8; ++ks) {
                uint32_t ah[2][4], al[2][4];
                uint32_t acb = (uint32_t)ks * 32 + aco;
                ldsm4(sb + SA_XH + swz(arow0,      acb), ah[0]);
                ldsm4(sb + SA_XH + swz(arow0 + 16, acb), ah[1]);
                ldsm4(sb + SA_XL + swz(arow0,      acb), al[0]);
                ldsm4(sb + SA_XL + swz(arow0 + 16, acb), al[1]);
                #pragma unroll
                for (int ng = 0; ng < 2; ++ng) {
                    uint32_t br  = (uint32_t)ks * 16 + brl;
                    uint32_t bcb = (uint32_t)(pc0 + ng * 16) * 2 + aco;
                    uint32_t bh[4], bl[4];
                    ldsm4t(sb + SA_WKH + swz(br, bcb), bh);
                    ldsm4t(sb + SA_WKL + swz(br, bcb), bl);
                    mma3(ka[0][2 * ng], ka[0][2 * ng + 1], ah[0], al[0], bh, bl);
                    mma3(ka[1][2 * ng], ka[1][2 * ng + 1], ah[1], al[1], bh, bl);
                    ldsm4t(sb + SA_WVH + swz(br, bcb), bh);
                    ldsm4t(sb + SA_WVL + swz(br, bcb), bl);
                    mma3(va[0][2 * ng], va[0][2 * ng + 1], ah[0], al[0], bh, bl);
                    mma3(va[1][2 * ng], va[1][2 * ng + 1], ah[1], al[1], bh, bl);
                }
            }
        }
        // ---- epilogue: k=exp(.+bk), v=.+bv -> hi/lo smem ----
        #pragma unroll
        for (int mb = 0; mb < 2; ++mb) {
            int r0 = pm0 + mb * 16 + er;
            #pragma unroll
            for (int nb = 0; nb < 4; ++nb) {
                int col = pc0 + nb * 8 + ec;
                float bk0 = sbk[col], bk1 = sbk[col + 1];
                float bv0 = sbv[col], bv1 = sbv[col + 1];
                uint32_t hp, lp;
                split2pack(fexp(ka[mb][nb][0] + bk0), fexp(ka[mb][nb][1] + bk1), hp, lp);
                *(uint32_t*)(smem + SA_KH + swz((uint32_t)r0, (uint32_t)col * 2)) = hp;
                *(uint32_t*)(smem + SA_KL + swz((uint32_t)r0, (uint32_t)col * 2)) = lp;
                split2pack(fexp(ka[mb][nb][2] + bk0), fexp(ka[mb][nb][3] + bk1), hp, lp);
                *(uint32_t*)(smem + SA_KH + swz((uint32_t)(r0 + 8), (uint32_t)col * 2)) = hp;
                *(uint32_t*)(smem + SA_KL + swz((uint32_t)(r0 + 8), (uint32_t)col * 2)) = lp;
                split2pack(va[mb][nb][0] + bv0, va[mb][nb][1] + bv1, hp, lp);
                *(uint32_t*)(smem + SA_VH + swz((uint32_t)r0, (uint32_t)col * 2)) = hp;
                *(uint32_t*)(smem + SA_VL + swz((uint32_t)r0, (uint32_t)col * 2)) = lp;
                split2pack(va[mb][nb][2] + bv0, va[mb][nb][3] + bv1, hp, lp);
                *(uint32_t*)(smem + SA_VH + swz((uint32_t)(r0 + 8), (uint32_t)col * 2)) = hp;
                *(uint32_t*)(smem + SA_VL + swz((uint32_t)(r0 + 8), (uint32_t)col * 2)) = lp;
            }
        }
        __syncthreads();   // K/V ready

        // ---- kv += k^T v, warp tile 32u x 64w ----
        {
            const uint32_t krl = (uint32_t)(((lane >> 4) & 1) * 8 + (lane & 7));
            const uint32_t vco = (uint32_t)((lane >> 4) & 1) * 16;
            #pragma unroll
            for (int ks = 0; ks < 4; ++ks) {
                uint32_t kah[2][4], kal[2][4];
                uint32_t kr = (uint32_t)ks * 16 + krl;
                #pragma unroll
                for (int mb = 0; mb < 2; ++mb) {
                    uint32_t ucb = (uint32_t)(u0 + mb * 16 + ((lane >> 3) & 1) * 8) * 2;
                    ldsm4t(sb + SA_KH + swz(kr, ucb), kah[mb]);
                    ldsm4t(sb + SA_KL + swz(kr, ucb), kal[mb]);
                }
                #pragma unroll
                for (int ng = 0; ng < 4; ++ng) {
                    uint32_t vr  = (uint32_t)(ks * 16 + (lane & 15));
                    uint32_t vcb = (uint32_t)(w0 + ng * 16) * 2 + vco;
                    uint32_t bh[4], bl[4];
                    ldsm4t(sb + SA_VH + swz(vr, vcb), bh);
                    ldsm4t(sb + SA_VL + swz(vr, vcb), bl);
                    mma3(kvacc[0][2 * ng], kvacc[0][2 * ng + 1], kah[0], kal[0], bh, bl);
                    mma3(kvacc[1][2 * ng], kvacc[1][2 * ng + 1], kah[1], kal[1], bh, bl);
                }
            }
        }
    }

    // final flush
    {
        float* kvb = g_kv + (size_t)bcur * 16384;
        #pragma unroll
        for (int mb = 0; mb < 2; ++mb) {
            int ur = u0 + mb * 16 + er;
            #pragma unroll
            for (int nb = 0; nb < 8; ++nb) {
                int col = w0 + nb * 8 + ec;
                atomicAdd(&kvb[ur * 128 + col],           kvacc[mb][nb][0]);
                atomicAdd(&kvb[ur * 128 + col + 1],       kvacc[mb][nb][1]);
                atomicAdd(&kvb[(ur + 8) * 128 + col],     kvacc[mb][nb][2]);
                atomicAdd(&kvb[(ur + 8) * 128 + col + 1], kvacc[mb][nb][3]);
            }
        }
    }
}

// ===========================================================================
// Stage B
// ===========================================================================
__global__ void __launch_bounds__(256, 1) stageB(
    const float* __restrict__ x,
    const float* __restrict__ Wq, const float* __restrict__ bq,
    float* __restrict__ out)
{
    extern __shared__ char smem[];
    const uint32_t sb = smem_u32(smem);
    const int tid = threadIdx.x, warp = tid >> 5, lane = tid & 31;

    const int task0 = (int)((long)blockIdx.x * TASKS / GRID);
    const int task1 = (int)((long)(blockIdx.x + 1) * TASKS / GRID);

    {
        const float2* wq2 = reinterpret_cast<const float2*>(Wq);
        for (int i = tid; i < 8192; i += 256) {
            uint32_t f  = (uint32_t)(i >> 6);
            uint32_t cb = (uint32_t)(i & 63) * 4;
            float2 a = wq2[i];
            uint32_t hp, lp;
            split2pack(a.x, a.y, hp, lp);
            *(uint32_t*)(smem + SB_WQH + swz(f, cb)) = hp;
            *(uint32_t*)(smem + SB_WQL + swz(f, cb)) = lp;
        }
        if (tid < 128)
            ((float*)(smem + SB_BQ))[tid] = bq[tid];
    }

    const int m0 = (warp >> 2) * 32, c0 = (warp & 3) * 32;
    const int er = lane >> 2, ec = 2 * (lane & 3);
    const float* sbq = (const float*)(smem + SB_BQ);
    const float4* xall = reinterpret_cast<const float4*>(x);

    float4 xr[8];
    #pragma unroll
    for (int ii = 0; ii < 8; ++ii)
        xr[ii] = xall[(size_t)task0 * 2048 + ii * 256 + tid];

    int bcur = -1;
    for (int t = task0; t < task1; ++t) {
        const int b = t >> 7;

        store_x_regs(smem, SB_XH, SB_XL, xr, tid);
        if (t + 1 < task1) {
            #pragma unroll
            for (int ii = 0; ii < 8; ++ii)
                xr[ii] = xall[(size_t)(t + 1) * 2048 + ii * 256 + tid];
        }
        __syncthreads();   // X ready; all warps past prior out phase (KV reads)

        if (b != bcur) {   // (re)load kv tile; visibility via next sync
            const float2* kv2 = reinterpret_cast<const float2*>(g_kv) + (size_t)b * 8192;
            for (int i = tid; i < 8192; i += 256) {
                uint32_t f  = (uint32_t)(i >> 6);
                uint32_t cb = (uint32_t)(i & 63) * 4;
                float2 a = kv2[i];
                uint32_t hp, lp;
                split2pack(a.x, a.y, hp, lp);
                *(uint32_t*)(smem + SB_KVH + swz(f, cb)) = hp;
                *(uint32_t*)(smem + SB_KVL + swz(f, cb)) = lp;
            }
            bcur = b;
        }

        // ---- q projection, warp tile 32x32 ----
        float pa[2][4][4];
        #pragma unroll
        for (int mb = 0; mb < 2; ++mb)
            #pragma unroll
            for (int nb = 0; nb < 4; ++nb)
                pa[mb][nb][0] = pa[mb][nb][1] = pa[mb][nb][2] = pa[mb][nb][3] = 0.f;
        {
            const uint32_t arow0 = (uint32_t)(m0 + (lane & 15));
            const uint32_t aco   = (uint32_t)((lane >> 4) & 1) * 16;
            const uint32_t brl   = (uint32_t)(lane & 15);
            #pragma unroll
            for (int ks = 0; ks < 8; ++ks) {
                uint32_t ah[2][4], al[2][4];
                uint32_t acb = (uint32_t)ks * 32 + aco;
                ldsm4(sb + SB_XH + swz(arow0,      acb), ah[0]);
                ldsm4(sb + SB_XH + swz(arow0 + 16, acb), ah[1]);
                ldsm4(sb + SB_XL + swz(arow0,      acb), al[0]);
                ldsm4(sb + SB_XL + swz(arow0 + 16, acb), al[1]);
                #pragma unroll
                for (int ng = 0; ng < 2; ++ng) {
                    uint32_t br  = (uint32_t)ks * 16 + brl;
                    uint32_t bcb = (uint32_t)(c0 + ng * 16) * 2 + aco;
                    uint32_t bh[4], bl[4];
                    ldsm4t(sb + SB_WQH + swz(br, bcb), bh);
                    ldsm4t(sb + SB_WQL + swz(br, bcb), bl);
                    mma3(pa[0][2 * ng], pa[0][2 * ng + 1], ah[0], al[0], bh, bl);
                    mma3(pa[1][2 * ng], pa[1][2 * ng + 1], ah[1], al[1], bh, bl);
                }
            }
        }
        // ---- epilogue: q = exp(.+bq) -> hi/lo smem ----
        #pragma unroll
        for (int mb = 0; mb < 2; ++mb) {
            int r0 = m0 + mb * 16 + er;
            #pragma unroll
            for (int nb = 0; nb < 4; ++nb) {
                int col = c0 + nb * 8 + ec;
                float b0 = sbq[col], b1 = sbq[col + 1];
                uint32_t hp, lp;
                split2pack(fexp(pa[mb][nb][0] + b0), fexp(pa[mb][nb][1] + b1), hp, lp);
                *(uint32_t*)(smem + SB_QH + swz((uint32_t)r0, (uint32_t)col * 2)) = hp;
                *(uint32_t*)(smem + SB_QL + swz((uint32_t)r0, (uint32_t)col * 2)) = lp;
                split2pack(fexp(pa[mb][nb][2] + b0), fexp(pa[mb][nb][3] + b1), hp, lp);
                *(uint32_t*)(smem + SB_QH + swz((uint32_t)(r0 + 8), (uint32_t)col * 2)) = hp;
                *(uint32_t*)(smem + SB_QL + swz((uint32_t)(r0 + 8), (uint32_t)col * 2)) = lp;
            }
        }
        __syncthreads();   // Q (and any reloaded KV) ready

        // ---- out = q @ kv, warp tile 32x32 ----
        float oa[2][4][4];
        #pragma unroll
        for (int mb = 0; mb < 2; ++mb)
            #pragma unroll
            for (int nb = 0; nb < 4; ++nb)
                oa[mb][nb][0] = oa[mb][nb][1] = oa[mb][nb][2] = oa[mb][nb][3] = 0.f;
        {
            const uint32_t arow0 = (uint32_t)(m0 + (lane & 15));
            const uint32_t aco   = (uint32_t)((lane >> 4) & 1) * 16;
            const uint32_t brl   = (uint32_t)(lane & 15);
            #pragma unroll
            for (int ks = 0; ks < 8; ++ks) {
                uint32_t ah[2][4], al[2][4];
                uint32_t acb = (uint32_t)ks * 32 + aco;
                ldsm4(sb + SB_QH + swz(arow0,      acb), ah[0]);
                ldsm4(sb + SB_QH + swz(arow0 + 16, acb), ah[1]);
                ldsm4(sb + SB_QL + swz(arow0,      acb), al[0]);
                ldsm4(sb + SB_QL + swz(arow0 + 16, acb), al[1]);
                #pragma unroll
                for (int ng = 0; ng < 2; ++ng) {
                    uint32_t br  = (uint32_t)ks * 16 + brl;
                    uint32_t bcb = (uint32_t)(c0 + ng * 16) * 2 + aco;
                    uint32_t bh[4], bl[4];
                    ldsm4t(sb + SB_KVH + swz(br, bcb), bh);
                    ldsm4t(sb + SB_KVL + swz(br, bcb), bl);
                    mma3(oa[0][2 * ng], oa[0][2 * ng + 1], ah[0], al[0], bh, bl);
                    mma3(oa[1][2 * ng], oa[1][2 * ng + 1], ah[1], al[1], bh, bl);
                }
            }
        }
        // store
        float* og = out + (size_t)t * 8192;
        #pragma unroll
        for (int mb = 0; mb < 2; ++mb) {
            int r0 = m0 + mb * 16 + er;
            #pragma unroll
            for (int nb = 0; nb < 4; ++nb) {
                int col = c0 + nb * 8 + ec;
                *(float2*)(og + (size_t)r0 * 128 + col)       = make_float2(oa[mb][nb][0], oa[mb][nb][1]);
                *(float2*)(og + (size_t)(r0 + 8) * 128 + col) = make_float2(oa[mb][nb][2], oa[mb][nb][3]);
            }
        }
    }
}

// ---------------------------------------------------------------------------
extern "C" void kernel_launch(void* const* d_in, const int* in_sizes, int n_in,
                              void* d_out, int out_size) {
    const float* x  = (const float*)d_in[0];
    const float* Wq = (const float*)d_in[1];
    const float* bq = (const float*)d_in[2];
    const float* Wk = (const float*)d_in[3];
    const float* bk = (const float*)d_in[4];
    const float* Wv = (const float*)d_in[5];
    const float* bv = (const float*)d_in[6];
    float* out = (float*)d_out;
    (void)in_sizes; (void)n_in; (void)out_size;

    cudaFuncSetAttribute(stageA, cudaFuncAttributeMaxDynamicSharedMemorySize, SA_SMEM);
    cudaFuncSetAttribute(stageB, cudaFuncAttributeMaxDynamicSharedMemorySize, SB_SMEM);

    zero_kv_kernel<<<256, 256>>>();
    stageA<<<GRID, 256, SA_SMEM>>>(x, Wk, bk, Wv, bv);
    stageB<<<GRID, 256, SB_SMEM>>>(x, Wq, bq, out);
}